// round 2
// baseline (speedup 1.0000x reference)
#include <cuda_runtime.h>
#include <math.h>

// Problem dims (fixed by reference)
#define BB   4096
#define EE   1024
#define HH   1024
#define CC   1024
#define DD   3072   // E + H + C

// Scratch (device globals: allocation-rule-safe)
__device__ float g_preact[(size_t)BB * 4 * HH];  // [B, 4H] gate preactivations (i,f,o,g)
__device__ float g_resid [(size_t)BB * EE];      // [B, E]  residual

// ---------------------------------------------------------------------------
// Generic 128x128x8 SIMT fp32 GEMM, 256 threads, 8x8 per thread.
// MODE 0: gates    out[b, n] = sum_k concat(A0,A1,A2)[b,k] * Wgate(n)[n%1024, k] + bgate(n)[n%1024]
//                  (K = 3072, N = 4096, ldo = 4096)
// MODE 1: resid    out[b, e] = sum_k concat(A0,A1)[b,k] * concatK(W0,W1)[e, k] + b0[e]+b1[e] + addend[b,e]
//                  (K = 2048, N = 1024, ldo = 1024)
// MODE 2: pred     out[b, e] = sum_k A0[b,k] * W0[e,k] + b0[e]
//                  (K = 1024, N = 1024, ldo = 1024)
// All source matrices have leading dim 1024 except MODE0 weights (ld = 3072).
// ---------------------------------------------------------------------------
template<int MODE>
__global__ __launch_bounds__(256)
void gemm128(const float* __restrict__ A0,
             const float* __restrict__ A1,
             const float* __restrict__ A2,
             const float* __restrict__ W0,
             const float* __restrict__ W1,
             const float* __restrict__ W2,
             const float* __restrict__ W3,
             const float* __restrict__ b0,
             const float* __restrict__ b1,
             const float* __restrict__ b2,
             const float* __restrict__ b3,
             const float* __restrict__ addend,
             float* __restrict__ out,
             int K, int ldo)
{
    constexpr int BM = 128, BN = 128, BK = 8;
    __shared__ float As[BK][BM];
    __shared__ float Bs[BK][BN];

    const int tid = threadIdx.x;
    const int m0  = blockIdx.y * BM;
    const int n0  = blockIdx.x * BN;

    // loader mapping: each thread fetches one float4 of A and one of W per K-tile
    const int lr  = tid >> 1;         // 0..127 : row within tile
    const int lc4 = (tid & 1) * 4;    // 0 or 4 : k offset within BK

    // compute mapping
    const int tx = tid & 15;          // n subtile
    const int ty = tid >> 4;          // m subtile

    // ---- A row base pointers (all A sources have ld = 1024) ----
    const float* aB0 = A0 + (size_t)(m0 + lr) * 1024;
    const float* aB1 = (MODE != 2) ? (A1 + (size_t)(m0 + lr) * 1024) : nullptr;
    const float* aB2 = (MODE == 0) ? (A2 + (size_t)(m0 + lr) * 1024) : nullptr;

    // ---- W row base pointers ----
    const float* wB0;
    const float* wB1 = nullptr;
    if (MODE == 0) {
        const int gate = n0 >> 10;
        const float* Wn = (gate == 0) ? W0 : (gate == 1) ? W1 : (gate == 2) ? W2 : W3;
        wB0 = Wn + (size_t)((n0 & 1023) + lr) * DD;   // ld = 3072
    } else if (MODE == 1) {
        wB0 = W0 + (size_t)(n0 + lr) * 1024;
        wB1 = W1 + (size_t)(n0 + lr) * 1024;
    } else {
        wB0 = W0 + (size_t)(n0 + lr) * 1024;
    }

    float acc[8][8];
#pragma unroll
    for (int i = 0; i < 8; i++)
#pragma unroll
        for (int j = 0; j < 8; j++) acc[i][j] = 0.0f;

    // fetch helpers (inlined per MODE)
    auto fetchA = [&](int kt) -> float4 {
        if (MODE == 0) {
            const int s  = kt >> 10;
            const int ko = (kt & 1023) + lc4;
            const float* p = (s == 0) ? aB0 : (s == 1) ? aB1 : aB2;
            return *reinterpret_cast<const float4*>(p + ko);
        } else if (MODE == 1) {
            const int s  = kt >> 10;
            const int ko = (kt & 1023) + lc4;
            const float* p = s ? aB1 : aB0;
            return *reinterpret_cast<const float4*>(p + ko);
        } else {
            return *reinterpret_cast<const float4*>(aB0 + kt + lc4);
        }
    };
    auto fetchB = [&](int kt) -> float4 {
        if (MODE == 0) {
            return *reinterpret_cast<const float4*>(wB0 + kt + lc4);
        } else if (MODE == 1) {
            const int s  = kt >> 10;
            const int ko = (kt & 1023) + lc4;
            const float* p = s ? wB1 : wB0;
            return *reinterpret_cast<const float4*>(p + ko);
        } else {
            return *reinterpret_cast<const float4*>(wB0 + kt + lc4);
        }
    };

    float4 ra = fetchA(0);
    float4 rb = fetchB(0);

    for (int kt = 0; kt < K; kt += BK) {
        // stage current tile into smem (transposed: [k][row])
        As[lc4 + 0][lr] = ra.x;  As[lc4 + 1][lr] = ra.y;
        As[lc4 + 2][lr] = ra.z;  As[lc4 + 3][lr] = ra.w;
        Bs[lc4 + 0][lr] = rb.x;  Bs[lc4 + 1][lr] = rb.y;
        Bs[lc4 + 2][lr] = rb.z;  Bs[lc4 + 3][lr] = rb.w;
        __syncthreads();

        // prefetch next tile into registers (hides gmem latency behind FMAs)
        if (kt + BK < K) {
            ra = fetchA(kt + BK);
            rb = fetchB(kt + BK);
        }

#pragma unroll
        for (int kk = 0; kk < BK; kk++) {
            float4 a0 = *reinterpret_cast<const float4*>(&As[kk][ty * 8]);
            float4 a1 = *reinterpret_cast<const float4*>(&As[kk][ty * 8 + 4]);
            float4 v0 = *reinterpret_cast<const float4*>(&Bs[kk][tx * 8]);
            float4 v1 = *reinterpret_cast<const float4*>(&Bs[kk][tx * 8 + 4]);
            float a[8] = {a0.x, a0.y, a0.z, a0.w, a1.x, a1.y, a1.z, a1.w};
            float b[8] = {v0.x, v0.y, v0.z, v0.w, v1.x, v1.y, v1.z, v1.w};
#pragma unroll
            for (int i = 0; i < 8; i++)
#pragma unroll
                for (int j = 0; j < 8; j++)
                    acc[i][j] = fmaf(a[i], b[j], acc[i][j]);
        }
        __syncthreads();
    }

    // -------- epilogue --------
    const int gm = m0 + ty * 8;
    const int gn = n0 + tx * 8;

    float bias[8];
    if (MODE == 0) {
        const int gate = n0 >> 10;
        const float* bb = (gate == 0) ? b0 : (gate == 1) ? b1 : (gate == 2) ? b2 : b3;
        const int nl = (gn & 1023);
#pragma unroll
        for (int j = 0; j < 8; j++) bias[j] = bb[nl + j];
    } else if (MODE == 1) {
#pragma unroll
        for (int j = 0; j < 8; j++) bias[j] = b0[gn + j] + b1[gn + j];
    } else {
#pragma unroll
        for (int j = 0; j < 8; j++) bias[j] = b0[gn + j];
    }

#pragma unroll
    for (int i = 0; i < 8; i++) {
        const size_t orow = (size_t)(gm + i) * ldo;
        if (MODE == 1) {
            const size_t arow = (size_t)(gm + i) * 1024;
#pragma unroll
            for (int j = 0; j < 8; j++)
                out[orow + gn + j] = acc[i][j] + bias[j] + addend[arow + gn + j];
        } else {
#pragma unroll
            for (int j = 0; j < 8; j++)
                out[orow + gn + j] = acc[i][j] + bias[j];
        }
    }
}

// ---------------------------------------------------------------------------
// Elementwise LSTM cell: i,f,o = sigmoid(pre), g = tanh(pre),
// cell = f*c_prev + i*g, hidden = o*tanh(cell)
// ---------------------------------------------------------------------------
__global__ void lstm_elem(const float* __restrict__ pre,
                          const float* __restrict__ cprev,
                          float* __restrict__ hidden,
                          float* __restrict__ cell)
{
    const int idx = blockIdx.x * blockDim.x + threadIdx.x;
    if (idx >= BB * HH) return;
    const int b = idx >> 10;
    const int h = idx & 1023;
    const size_t base = (size_t)b * (4 * HH) + h;

    const float pi = pre[base];
    const float pf = pre[base + 1024];
    const float po = pre[base + 2048];
    const float pg = pre[base + 3072];

    const float si = 1.0f / (1.0f + expf(-pi));
    const float sf = 1.0f / (1.0f + expf(-pf));
    const float so = 1.0f / (1.0f + expf(-po));
    const float tg = tanhf(pg);

    const float c = sf * cprev[idx] + si * tg;
    const float hv = so * tanhf(c);

    cell[idx]   = c;
    hidden[idx] = hv;
}

extern "C" void kernel_launch(void* const* d_in, const int* in_sizes, int n_in,
                              void* d_out, int out_size)
{
    (void)in_sizes; (void)n_in; (void)out_size;

    const float* emb = (const float*)d_in[0];
    const float* hid = (const float*)d_in[1];
    const float* cpr = (const float*)d_in[2];
    const float* ctx = (const float*)d_in[3];
    const float* Wi  = (const float*)d_in[4];  const float* bi = (const float*)d_in[5];
    const float* Wf  = (const float*)d_in[6];  const float* bf = (const float*)d_in[7];
    const float* Wo  = (const float*)d_in[8];  const float* bo = (const float*)d_in[9];
    const float* Wg  = (const float*)d_in[10]; const float* bg = (const float*)d_in[11];
    const float* Wc  = (const float*)d_in[12]; const float* bc = (const float*)d_in[13];
    const float* Wh  = (const float*)d_in[14]; const float* bh = (const float*)d_in[15];
    const float* Wp  = (const float*)d_in[16]; const float* bp = (const float*)d_in[17];

    float* out     = (float*)d_out;
    float* pred    = out;                                   // [B, E]
    float* hiddenO = out + (size_t)BB * EE;                 // [B, H]
    float* cellO   = hiddenO + (size_t)BB * HH;             // [B, H]

    float* pre_ptr   = nullptr;
    float* resid_ptr = nullptr;
    cudaGetSymbolAddress((void**)&pre_ptr,   g_preact);
    cudaGetSymbolAddress((void**)&resid_ptr, g_resid);

    // 1) gate preactivations: [B, 4H] = concat(emb,hid,ctx) @ [Wi;Wf;Wo;Wg]^T + b
    {
        dim3 grid(4 * HH / 128, BB / 128);  // (32, 32)
        gemm128<0><<<grid, 256>>>(emb, hid, ctx,
                                  Wi, Wf, Wo, Wg,
                                  bi, bf, bo, bg,
                                  nullptr, pre_ptr, DD, 4 * HH);
    }

    // 2) elementwise LSTM cell -> hidden, cell (written straight into the output)
    {
        const int n = BB * HH;
        lstm_elem<<<(n + 255) / 256, 256>>>(pre_ptr, cpr, hiddenO, cellO);
    }

    // 3) resid = emb + hidden @ Wh^T + bh + ctx @ Wc^T + bc   (K fused to 2048)
    {
        dim3 grid(EE / 128, BB / 128);  // (8, 32)
        gemm128<1><<<grid, 256>>>(hiddenO, ctx, nullptr,
                                  Wh, Wc, nullptr, nullptr,
                                  bh, bc, nullptr, nullptr,
                                  emb, resid_ptr, HH + CC, EE);
    }

    // 4) prediction = resid @ Wp^T + bp  -> out[0 : B*E]
    {
        dim3 grid(EE / 128, BB / 128);  // (8, 32)
        gemm128<2><<<grid, 256>>>(resid_ptr, nullptr, nullptr,
                                  Wp, nullptr, nullptr, nullptr,
                                  bp, nullptr, nullptr, nullptr,
                                  nullptr, pred, EE, EE);
    }
}

// round 4
// speedup vs baseline: 2.4046x; 2.4046x over previous
#include <cuda_runtime.h>
#include <cstdint>
#include <math.h>

#define BB 4096
#define EE 1024
#define HH 1024
#define CC 1024
#define DD 3072

// scratch (device globals: allocation-rule-safe)
__device__ float g_preact[(size_t)BB * 4 * HH];   // [B, 4H]
__device__ float g_resid [(size_t)BB * EE];       // [B, E]

__device__ __forceinline__ float f2tf(float x) {
    uint32_t r; asm("cvt.rna.tf32.f32 %0, %1;" : "=r"(r) : "f"(x));
    return __uint_as_float(r);
}

__device__ __forceinline__ void mma_tf32(float* c, const uint32_t* a, const uint32_t* b) {
    asm volatile(
        "mma.sync.aligned.m16n8k8.row.col.f32.tf32.tf32.f32 "
        "{%0,%1,%2,%3}, {%4,%5,%6,%7}, {%8,%9}, {%0,%1,%2,%3};"
        : "+f"(c[0]), "+f"(c[1]), "+f"(c[2]), "+f"(c[3])
        : "r"(a[0]), "r"(a[1]), "r"(a[2]), "r"(a[3]), "r"(b[0]), "r"(b[1]));
}

// ---------------------------------------------------------------------------
// tf32 warp-MMA GEMM.  CTA tile 128x128, BK=32.  256 threads, 8 warps (4M x 2N),
// warp tile 32x64.  Fragment-major smem (A: LDS.128/tile, B: LDS.64/tile).
// MODE 0: gates  out[b,n] = concat(emb,hid,ctx) @ Wgate(n)^T + bgate   (K=3072, N=4096)
// MODE 1: resid  out[b,e] = concat(hid,ctx) @ [Wh|Wc]^T + bh+bc + emb  (K=2048, N=1024)
// MODE 2: pred   out[b,e] = A @ Wp^T + bp                              (K=1024, N=1024)
// ---------------------------------------------------------------------------
template<int MODE>
__global__ __launch_bounds__(256)
void mma_gemm(const float* __restrict__ A0, const float* __restrict__ A1,
              const float* __restrict__ A2,
              const float* __restrict__ W0, const float* __restrict__ W1,
              const float* __restrict__ W2, const float* __restrict__ W3,
              const float* __restrict__ b0, const float* __restrict__ b1,
              const float* __restrict__ b2, const float* __restrict__ b3,
              const float* __restrict__ addend, float* __restrict__ out,
              int K, int ldo)
{
    extern __shared__ float smf[];            // 2 * (4096 A + 4096 B) floats = 64KB
    const int tid  = threadIdx.x;
    const int m0   = blockIdx.y * 128;
    const int n0   = blockIdx.x * 128;
    const int w    = tid >> 5, lane = tid & 31;
    const int wm   = w >> 1,  wn   = w & 1;

    // staging mapping: thread covers rows (tid>>3)+t*32, k-quad q = tid&7
    const int q    = tid & 7;
    const int rA   = tid >> 3;

    // MODE0 per-gate select (BN=128 tiles never straddle a gate: n0%1024 + 128 <= 1024)
    const float* Wsel = W0; const float* bsel = b0;
    if (MODE == 0) {
        const int g = n0 >> 10;
        Wsel = (g == 0) ? W0 : (g == 1) ? W1 : (g == 2) ? W2 : W3;
        bsel = (g == 0) ? b0 : (g == 1) ? b1 : (g == 2) ? b2 : b3;
    }
    const int nloc0 = n0 & 1023;

    float acc[2][8][4];
#pragma unroll
    for (int i = 0; i < 2; i++)
#pragma unroll
        for (int j = 0; j < 8; j++)
#pragma unroll
            for (int v = 0; v < 4; v++) acc[i][j][v] = 0.0f;

    const int nK = K >> 5;

    // ---- fetch helpers (registers) ----
    auto fetchA = [&](int kt, int t) -> float4 {
        const int kbase = kt * 32;
        const int row   = m0 + rA + t * 32;
        if (MODE == 0) {
            const int ks = kbase >> 10, kl = kbase & 1023;
            const float* s = (ks == 0) ? A0 : (ks == 1) ? A1 : A2;
            return *reinterpret_cast<const float4*>(s + (size_t)row * 1024 + kl + q * 4);
        } else if (MODE == 1) {
            const int ks = kbase >> 10, kl = kbase & 1023;
            const float* s = ks ? A1 : A0;
            return *reinterpret_cast<const float4*>(s + (size_t)row * 1024 + kl + q * 4);
        } else {
            return *reinterpret_cast<const float4*>(A0 + (size_t)row * 1024 + kbase + q * 4);
        }
    };
    auto fetchB = [&](int kt, int t) -> float4 {
        const int kbase = kt * 32;
        const int nr    = rA + t * 32;
        if (MODE == 0) {
            return *reinterpret_cast<const float4*>(
                Wsel + (size_t)(nloc0 + nr) * DD + kbase + q * 4);
        } else if (MODE == 1) {
            const int ks = kbase >> 10, kl = kbase & 1023;
            const float* s = ks ? W1 : W0;
            return *reinterpret_cast<const float4*>(s + (size_t)(n0 + nr) * 1024 + kl + q * 4);
        } else {
            return *reinterpret_cast<const float4*>(W0 + (size_t)(n0 + nr) * 1024 + kbase + q * 4);
        }
    };

    float4 ra[4], rb[4];
#pragma unroll
    for (int t = 0; t < 4; t++) { ra[t] = fetchA(0, t); rb[t] = fetchB(0, t); }

    for (int kt = 0; kt < nK; kt++) {
        const int p = kt & 1;
        float* Abuf = smf + p * 8192;
        float* Bbuf = Abuf + 4096;

        // ---- store staged tile (fragment-major, tf32-converted) ----
#pragma unroll
        for (int t = 0; t < 4; t++) {
            const int row = rA + t * 32;
            {   // A: tile (k8*8 + row/16), lane (row%8)*4+j, slot 2*(q&1)+((row>>3)&1)
                const int k8 = q >> 1;
                const int s  = ((q & 1) << 1) | ((row >> 3) & 1);
                float* dst = Abuf + (k8 * 8 + (row >> 4)) * 128 + (row & 7) * 16 + s;
                dst[0]  = f2tf(ra[t].x); dst[4]  = f2tf(ra[t].y);
                dst[8]  = f2tf(ra[t].z); dst[12] = f2tf(ra[t].w);
            }
            {   // B: tile (k8*16 + row/8), lane (row%8)*4+j, slot q&1
                const int k8 = q >> 1;
                const int s  = q & 1;
                float* dst = Bbuf + (k8 * 16 + (row >> 3)) * 64 + (row & 7) * 8 + s;
                dst[0] = f2tf(rb[t].x); dst[2] = f2tf(rb[t].y);
                dst[4] = f2tf(rb[t].z); dst[6] = f2tf(rb[t].w);
            }
        }
        __syncthreads();

        // prefetch next k-tile while computing this one
        if (kt + 1 < nK) {
#pragma unroll
            for (int t = 0; t < 4; t++) { ra[t] = fetchA(kt + 1, t); rb[t] = fetchB(kt + 1, t); }
        }

        // ---- compute: 4 k8-steps x (2 m-tiles x 8 n-tiles) mma ----
#pragma unroll
        for (int k8 = 0; k8 < 4; k8++) {
            uint32_t af[2][4];
#pragma unroll
            for (int mi = 0; mi < 2; mi++) {
                float4 v = *reinterpret_cast<const float4*>(
                    Abuf + (k8 * 8 + wm * 2 + mi) * 128 + lane * 4);
                af[mi][0] = __float_as_uint(v.x); af[mi][1] = __float_as_uint(v.y);
                af[mi][2] = __float_as_uint(v.z); af[mi][3] = __float_as_uint(v.w);
            }
            uint32_t bf[8][2];
#pragma unroll
            for (int nj = 0; nj < 8; nj++) {
                float2 v = *reinterpret_cast<const float2*>(
                    Bbuf + (k8 * 16 + wn * 8 + nj) * 64 + lane * 2);
                bf[nj][0] = __float_as_uint(v.x); bf[nj][1] = __float_as_uint(v.y);
            }
#pragma unroll
            for (int mi = 0; mi < 2; mi++)
#pragma unroll
                for (int nj = 0; nj < 8; nj++)
                    mma_tf32(acc[mi][nj], af[mi], bf[nj]);
        }
        __syncthreads();
    }

    // ---- epilogue: direct STG.64 (32B sector-aligned segments) ----
    const int gr = lane >> 2;            // group row 0..7
    const int gc = (lane & 3) * 2;       // col pair
#pragma unroll
    for (int mi = 0; mi < 2; mi++) {
        const int gm = m0 + wm * 32 + mi * 16 + gr;
#pragma unroll
        for (int nj = 0; nj < 8; nj++) {
            const int gn = n0 + wn * 64 + nj * 8 + gc;
            float bv0, bv1;
            if (MODE == 0)      { bv0 = bsel[(gn & 1023)]; bv1 = bsel[(gn & 1023) + 1]; }
            else if (MODE == 1) { bv0 = b0[gn] + b1[gn];   bv1 = b0[gn + 1] + b1[gn + 1]; }
            else                { bv0 = b0[gn];            bv1 = b0[gn + 1]; }

            float2 r0 = make_float2(acc[mi][nj][0] + bv0, acc[mi][nj][1] + bv1);
            float2 r1 = make_float2(acc[mi][nj][2] + bv0, acc[mi][nj][3] + bv1);
            if (MODE == 1) {
                const float2 a0 = *reinterpret_cast<const float2*>(
                    addend + (size_t)gm * 1024 + gn);
                const float2 a1 = *reinterpret_cast<const float2*>(
                    addend + (size_t)(gm + 8) * 1024 + gn);
                r0.x += a0.x; r0.y += a0.y; r1.x += a1.x; r1.y += a1.y;
            }
            *reinterpret_cast<float2*>(out + (size_t)gm * ldo + gn)       = r0;
            *reinterpret_cast<float2*>(out + (size_t)(gm + 8) * ldo + gn) = r1;
        }
    }
}

// ---------------------------------------------------------------------------
// Elementwise LSTM cell
// ---------------------------------------------------------------------------
__device__ __forceinline__ float sigf(float x) { return 1.0f / (1.0f + __expf(-x)); }
__device__ __forceinline__ float tanhfast(float x) { return 2.0f * sigf(2.0f * x) - 1.0f; }

__global__ void lstm_elem(const float4* __restrict__ pre,
                          const float4* __restrict__ cprev,
                          float4* __restrict__ hidden,
                          float4* __restrict__ cell)
{
    const int idx = blockIdx.x * blockDim.x + threadIdx.x;   // BB*HH/4
    const int b  = idx >> 8;
    const int h4 = idx & 255;
    const size_t base = (size_t)b * 1024;
    const float4 pi = pre[base + h4];
    const float4 pf = pre[base + 256 + h4];
    const float4 po = pre[base + 512 + h4];
    const float4 pg = pre[base + 768 + h4];
    const float4 cp = cprev[idx];

    float c0 = sigf(pf.x) * cp.x + sigf(pi.x) * tanhfast(pg.x);
    float c1 = sigf(pf.y) * cp.y + sigf(pi.y) * tanhfast(pg.y);
    float c2 = sigf(pf.z) * cp.z + sigf(pi.z) * tanhfast(pg.z);
    float c3 = sigf(pf.w) * cp.w + sigf(pi.w) * tanhfast(pg.w);

    cell[idx]   = make_float4(c0, c1, c2, c3);
    hidden[idx] = make_float4(sigf(po.x) * tanhfast(c0), sigf(po.y) * tanhfast(c1),
                              sigf(po.z) * tanhfast(c2), sigf(po.w) * tanhfast(c3));
}

// ---------------------------------------------------------------------------
extern "C" void kernel_launch(void* const* d_in, const int* in_sizes, int n_in,
                              void* d_out, int out_size)
{
    (void)in_sizes; (void)n_in; (void)out_size;

    const float* emb = (const float*)d_in[0];
    const float* hid = (const float*)d_in[1];
    const float* cpr = (const float*)d_in[2];
    const float* ctx = (const float*)d_in[3];
    const float* Wi  = (const float*)d_in[4];  const float* bi = (const float*)d_in[5];
    const float* Wf  = (const float*)d_in[6];  const float* bf = (const float*)d_in[7];
    const float* Wo  = (const float*)d_in[8];  const float* bo = (const float*)d_in[9];
    const float* Wg  = (const float*)d_in[10]; const float* bg = (const float*)d_in[11];
    const float* Wc  = (const float*)d_in[12]; const float* bc = (const float*)d_in[13];
    const float* Wh  = (const float*)d_in[14]; const float* bh = (const float*)d_in[15];
    const float* Wp  = (const float*)d_in[16]; const float* bp = (const float*)d_in[17];

    float* out     = (float*)d_out;
    float* pred    = out;                        // [B, E]
    float* hiddenO = out + (size_t)BB * EE;      // [B, H]
    float* cellO   = hiddenO + (size_t)BB * HH;  // [B, H]

    float* pre_ptr = nullptr, *resid_ptr = nullptr;
    cudaGetSymbolAddress((void**)&pre_ptr,   g_preact);
    cudaGetSymbolAddress((void**)&resid_ptr, g_resid);

    const int SMEM = 2 * 8192 * sizeof(float);   // 64KB
    cudaFuncSetAttribute(mma_gemm<0>, cudaFuncAttributeMaxDynamicSharedMemorySize, SMEM);
    cudaFuncSetAttribute(mma_gemm<1>, cudaFuncAttributeMaxDynamicSharedMemorySize, SMEM);
    cudaFuncSetAttribute(mma_gemm<2>, cudaFuncAttributeMaxDynamicSharedMemorySize, SMEM);

    // 1) gates: [B,4H]
    mma_gemm<0><<<dim3(32, 32), 256, SMEM>>>(
        emb, hid, ctx, Wi, Wf, Wo, Wg, bi, bf, bo, bg,
        nullptr, pre_ptr, DD, 4 * HH);

    // 2) cell update
    lstm_elem<<<4096, 256>>>((const float4*)pre_ptr, (const float4*)cpr,
                             (float4*)hiddenO, (float4*)cellO);

    // 3) resid = emb + hidden@Wh^T + bh + ctx@Wc^T + bc
    mma_gemm<1><<<dim3(8, 32), 256, SMEM>>>(
        hiddenO, ctx, nullptr, Wh, Wc, nullptr, nullptr, bh, bc, nullptr, nullptr,
        emb, resid_ptr, HH + CC, EE);

    // 4) prediction = resid @ Wp^T + bp
    mma_gemm<2><<<dim3(8, 32), 256, SMEM>>>(
        resid_ptr, nullptr, nullptr, Wp, nullptr, nullptr, nullptr,
        bp, nullptr, nullptr, nullptr, nullptr, pred, EE, EE);
}